// round 7
// baseline (speedup 1.0000x reference)
#include <cuda_runtime.h>
#include <cstdint>

// GramsEmbedding: out[b,s,:] = sum over UNIQUE v in {idx[0,b,s], idx[1,b,s]} of weight[v,:]
// K=2, B=2, S=1024, V=32000, D=128.
//
// Operating point (established R4/R6): 131072 threads, 4 independent weight
// gathers per thread, int2-compressed idx loads. This round's micro-levers:
//  - 128-thread CTAs (1024 CTAs, ~7/SM) for finer ramp/drain granularity
//  - streaming stores (st.global.cs): output is write-once, keep it out of
//    the L2 working set competing with the gather stream.

#define ROWS      2048      // B * S
#define D         128
#define THREADS   128

__global__ __launch_bounds__(THREADS, 16)
void grams_embedding_kernel(const int2* __restrict__ idx2,   // [2][1024] int2
                            const float* __restrict__ w,     // [32000][128]
                            float* __restrict__ out)         // [2048][128]
{
    int t   = blockIdx.x * THREADS + threadIdx.x;    // 0 .. 131071
    int g   = t >> 7;                                 // row pair 0 .. 1023
    int col = t & 127;                                // 0 .. 127

    // Level 1: two independent 8B idx loads (warp-broadcast, mostly L2-hit)
    int2 ia = __ldg(&idx2[g]);               // gram0 indices, rows 2g / 2g+1
    int2 ib = __ldg(&idx2[g + ROWS / 2]);    // gram1 indices, rows 2g / 2g+1

    // Level 2: 4 independent gathers (coalesced 128B per warp), 32-bit offsets
    float a0 = __ldg(&w[ia.x * D + col]);
    float a1 = __ldg(&w[ia.y * D + col]);
    float b0 = __ldg(&w[ib.x * D + col]);
    float b1 = __ldg(&w[ib.y * D + col]);

    int base = (g << 1) * D + col;           // row 2g, this col
    __stcs(&out[base    ], a0 + (ib.x != ia.x ? b0 : 0.0f));
    __stcs(&out[base + D], a1 + (ib.y != ia.y ? b1 : 0.0f));
}

extern "C" void kernel_launch(void* const* d_in, const int* in_sizes, int n_in,
                              void* d_out, int out_size)
{
    const int2*  idx2 = (const int2*)d_in[0];
    const float* w    = (const float*)d_in[1];
    float*       out  = (float*)d_out;

    grams_embedding_kernel<<<(ROWS / 2 * D) / THREADS, THREADS>>>(idx2, w, out);
}

// round 8
// speedup vs baseline: 1.0103x; 1.0103x over previous
#include <cuda_runtime.h>
#include <cstdint>

// GramsEmbedding: out[b,s,:] = sum over UNIQUE v in {idx[0,b,s], idx[1,b,s]} of weight[v,:]
// K=2, B=2, S=1024, V=32000, D=128.
//
// Best-measured configuration (R7, kernel 4.99us):
//  - 131072 threads: one thread per (row-pair, column); 4 independent weight
//    gathers per thread (the measured chip-wide MLP sweet spot)
//  - level-1 idx loads compressed to two int2 (8B, warp-broadcast)
//  - 128-thread CTAs (1024 CTAs, ~7/SM) for fine ramp/drain granularity
//  - streaming stores (st.global.cs): write-once output stays out of the
//    L2 working set competing with the gather stream.

#define ROWS      2048u     // B * S
#define D         128u
#define THREADS   128u

__global__ __launch_bounds__(THREADS, 16)
void grams_embedding_kernel(const int2* __restrict__ idx2,   // [2][1024] int2
                            const float* __restrict__ w,     // [32000][128]
                            float* __restrict__ out)         // [2048][128]
{
    unsigned t   = blockIdx.x * THREADS + threadIdx.x;   // 0 .. 131071
    unsigned g   = t >> 7;                                // row pair 0 .. 1023
    unsigned col = t & 127u;                              // 0 .. 127

    // Level 1: two independent 8B idx loads (warp-broadcast)
    int2 ia = __ldg(&idx2[g]);                // gram0 indices, rows 2g / 2g+1
    int2 ib = __ldg(&idx2[g + ROWS / 2]);     // gram1 indices, rows 2g / 2g+1

    // Level 2: 4 independent gathers (coalesced 128B per warp), 32-bit offsets
    float a0 = __ldg(&w[(unsigned)ia.x * D + col]);
    float a1 = __ldg(&w[(unsigned)ia.y * D + col]);
    float b0 = __ldg(&w[(unsigned)ib.x * D + col]);
    float b1 = __ldg(&w[(unsigned)ib.y * D + col]);

    unsigned base = (g << 1) * D + col;       // row 2g, this col
    __stcs(&out[base    ], a0 + (ib.x != ia.x ? b0 : 0.0f));
    __stcs(&out[base + D], a1 + (ib.y != ia.y ? b1 : 0.0f));
}

extern "C" void kernel_launch(void* const* d_in, const int* in_sizes, int n_in,
                              void* d_out, int out_size)
{
    const int2*  idx2 = (const int2*)d_in[0];
    const float* w    = (const float*)d_in[1];
    float*       out  = (float*)d_out;

    grams_embedding_kernel<<<(ROWS / 2 * D) / THREADS, THREADS>>>(idx2, w, out);
}

// round 9
// speedup vs baseline: 1.0260x; 1.0156x over previous
#include <cuda_runtime.h>
#include <cstdint>

// GramsEmbedding: out[b,s,:] = sum over UNIQUE v in {idx[0,b,s], idx[1,b,s]} of weight[v,:]
// K=2, B=2, S=1024, V=32000, D=128.
//
// FINAL kernel — best-measured configuration (4.99us kernel dur, R7):
//  - 131072 threads: one thread per (row-pair, column); 4 independent weight
//    gathers per thread (measured chip-wide MLP sweet spot across R2/R4/R5)
//  - level-1 idx loads compressed to two int2 (8B, warp-broadcast)
//  - 128-thread CTAs (1024 CTAs, ~7/SM) for fine ramp/drain granularity
//  - streaming stores (st.global.cs): write-once output stays out of the
//    L2 working set competing with the gather stream.
// Remaining time is launch ramp (~T_ovh) + one cold idx->gather round trip;
// both invariant to kernel shape (R4/R6/R7/R8 all within +/-0.2us).

#define ROWS      2048u     // B * S
#define D         128u
#define THREADS   128u

__global__ __launch_bounds__(THREADS, 16)
void grams_embedding_kernel(const int2* __restrict__ idx2,   // [2][1024] int2
                            const float* __restrict__ w,     // [32000][128]
                            float* __restrict__ out)         // [2048][128]
{
    unsigned t   = blockIdx.x * THREADS + threadIdx.x;   // 0 .. 131071
    unsigned g   = t >> 7;                                // row pair 0 .. 1023
    unsigned col = t & 127u;                              // 0 .. 127

    // Level 1: two independent 8B idx loads (warp-broadcast)
    int2 ia = __ldg(&idx2[g]);                // gram0 indices, rows 2g / 2g+1
    int2 ib = __ldg(&idx2[g + ROWS / 2]);     // gram1 indices, rows 2g / 2g+1

    // Level 2: 4 independent gathers (coalesced 128B per warp), 32-bit offsets
    float a0 = __ldg(&w[(unsigned)ia.x * D + col]);
    float a1 = __ldg(&w[(unsigned)ia.y * D + col]);
    float b0 = __ldg(&w[(unsigned)ib.x * D + col]);
    float b1 = __ldg(&w[(unsigned)ib.y * D + col]);

    unsigned base = (g << 1) * D + col;       // row 2g, this col
    __stcs(&out[base    ], a0 + (ib.x != ia.x ? b0 : 0.0f));
    __stcs(&out[base + D], a1 + (ib.y != ia.y ? b1 : 0.0f));
}

extern "C" void kernel_launch(void* const* d_in, const int* in_sizes, int n_in,
                              void* d_out, int out_size)
{
    const int2*  idx2 = (const int2*)d_in[0];
    const float* w    = (const float*)d_in[1];
    float*       out  = (float*)d_out;

    grams_embedding_kernel<<<(ROWS / 2 * D) / THREADS, THREADS>>>(idx2, w, out);
}